// round 16
// baseline (speedup 1.0000x reference)
#include <cuda_runtime.h>
#include <cuda_fp16.h>
#include <math_constants.h>
#include <cstdint>

// Problem shape (fixed)
#define BB 2
#define LL 2048
#define HH 16
#define EE 64
#define DD 64
#define DMODEL 512
#define DHID 256

__device__ float g_part[2][BB * LL];
__device__ float g_mom[BB * LL];
// w1 fp16 hi/lo, layout [k][group(0..3)][32 u32], chunk-swizzled by (k&7)
__device__ __align__(16) uint32_t g_w1h[DMODEL * 128];
__device__ __align__(16) uint32_t g_w1l[DMODEL * 128];
// fp16 hi-only, head-major, PRE-SWIZZLED: [b][h][l][32 u32]
__device__ __align__(16) uint32_t g_q16[BB * HH * LL * 32];
__device__ __align__(16) uint32_t g_k16[BB * HH * LL * 32];
__device__ __align__(16) uint32_t g_v16[BB * HH * LL * 32];

__device__ __forceinline__ void splitH2(float x0, float x1, uint32_t& hi,
                                        uint32_t& lo) {
  __half2 h = __floats2half2_rn(x0, x1);
  float2 hf = __half22float2(h);
  __half2 l = __floats2half2_rn(x0 - hf.x, x1 - hf.y);
  hi = *(uint32_t*)&h;
  lo = *(uint32_t*)&l;
}
__device__ __forceinline__ uint32_t packH2(float x0, float x1) {
  __half2 h = __floats2half2_rn(x0, x1);
  return *(uint32_t*)&h;
}
__device__ __forceinline__ float ex2f(float x) {
  float r;
  asm("ex2.approx.ftz.f32 %0, %1;" : "=f"(r) : "f"(x));
  return r;
}
__device__ __forceinline__ uint32_t smem_u32(const void* p) {
  uint32_t a;
  asm("{ .reg .u64 t; cvta.to.shared.u64 t, %1; cvt.u32.u64 %0, t; }"
      : "=r"(a) : "l"(p));
  return a;
}
// swizzled u32 col within a 32-u32 row
__device__ __forceinline__ int swz_c(int row, int col) {
  return (col & 3) + ((((col >> 2) ^ row) & 7) << 2);
}

#define MMA16816(d, a0, a1, a2, a3, b0, b1)                                 \
  asm volatile(                                                             \
      "mma.sync.aligned.m16n8k16.row.col.f32.f16.f16.f32 "                  \
      "{%0,%1,%2,%3}, {%4,%5,%6,%7}, {%8,%9}, {%0,%1,%2,%3};"               \
      : "+f"((d)[0]), "+f"((d)[1]), "+f"((d)[2]), "+f"((d)[3])              \
      : "r"(a0), "r"(a1), "r"(a2), "r"(a3), "r"(b0), "r"(b1))

#define LDMX4(r0, r1, r2, r3, addr)                                         \
  asm volatile(                                                             \
      "ldmatrix.sync.aligned.m8n8.x4.shared.b16 {%0,%1,%2,%3}, [%4];"       \
      : "=r"(r0), "=r"(r1), "=r"(r2), "=r"(r3) : "r"(addr))

#define LDMX4T(r0, r1, r2, r3, addr)                                        \
  asm volatile(                                                             \
      "ldmatrix.sync.aligned.m8n8.x4.trans.shared.b16 {%0,%1,%2,%3}, [%4];" \
      : "=r"(r0), "=r"(r1), "=r"(r2), "=r"(r3) : "r"(addr))

// ============================================================================
// Kernel 0a: convert w1 to fp16 hi/lo scratch (for MLP)
// ============================================================================
__global__ __launch_bounds__(256) void wconv_kernel(const float* __restrict__ w1) {
  int idx = blockIdx.x * 256 + threadIdx.x;
  int k = idx >> 5;
  int r5 = idx & 31;
  int g = r5 >> 3, ch = r5 & 7;
  const float4* src = (const float4*)(w1 + (size_t)k * DHID + g * 64 + ch * 8);
  float4 a = src[0], b = src[1];
  uint32_t h0, l0, h1, l1, h2, l2, h3, l3;
  splitH2(a.x, a.y, h0, l0);
  splitH2(a.z, a.w, h1, l1);
  splitH2(b.x, b.y, h2, l2);
  splitH2(b.z, b.w, h3, l3);
  size_t dst = ((size_t)(k * 4 + g)) * 32 + ((ch ^ (k & 7)) << 2);
  *(uint4*)(g_w1h + dst) = make_uint4(h0, h1, h2, h3);
  *(uint4*)(g_w1l + dst) = make_uint4(l0, l1, l2, l3);
}

// ============================================================================
// Kernel 0b: convert Q*sc/K/V to fp16 hi-only (pre-swizzled) + momentum.
// Runs AFTER mlp_tc so g_part is ready. Block = one (b,l).
// ============================================================================
__global__ __launch_bounds__(256) void qkvconv_kernel(
    const float* __restrict__ qg, const float* __restrict__ kg,
    const float* __restrict__ vg) {
  int bl = blockIdx.x;
  int b = bl >> 11, l = bl & 2047;
  int tid = threadIdx.x;
  int h = tid >> 4;
  int e4 = tid & 15;

  const float sc = 0.125f * 1.44269504f;
  size_t gsrc = ((size_t)(b * LL + l) * HH + h) * EE + e4 * 4;
  size_t gdst = ((size_t)(b * HH + h) * LL + l) * 32;
  int scol = swz_c(l & 7, 2 * e4);

  float4 xq = *(const float4*)(qg + gsrc);
  *(uint2*)(g_q16 + gdst + scol) =
      make_uint2(packH2(xq.x * sc, xq.y * sc), packH2(xq.z * sc, xq.w * sc));
  float4 xk = *(const float4*)(kg + gsrc);
  *(uint2*)(g_k16 + gdst + scol) =
      make_uint2(packH2(xk.x, xk.y), packH2(xk.z, xk.w));
  float4 xv = *(const float4*)(vg + gsrc);
  *(uint2*)(g_v16 + gdst + scol) =
      make_uint2(packH2(xv.x, xv.y), packH2(xv.z, xv.w));

  if (tid == 0) {
    float m = 0.f;
    if (l > 0)
      m = (g_part[0][bl] + g_part[1][bl]) -
          (g_part[0][bl - 1] + g_part[1][bl - 1]);
    g_mom[bl] = m;
  }
}

// ============================================================================
// Kernel 1: tensor-core MLP, N-split (unchanged from R12 winner)
// ============================================================================
#define M_RAW 0
#define M_BH 2048
#define M_BL 6144
#define M_RED 10240
#define MLP_SMEM ((10240 + 512) * 4)

__global__ __launch_bounds__(256) void mlp_tc_kernel(
    const float* __restrict__ raw, const float* __restrict__ b1,
    const float* __restrict__ w2) {
  extern __shared__ uint32_t ms[];
  uint32_t sbm = smem_u32(ms);
  int tid = threadIdx.x;
  int w = tid >> 5, lane = tid & 31;
  int quad = lane >> 2, four = lane & 3;
  int m0 = blockIdx.x * 64;
  int nh = blockIdx.y;

  float sC[4][2][4];
#pragma unroll
  for (int mt = 0; mt < 4; mt++)
#pragma unroll
    for (int nt = 0; nt < 2; nt++)
#pragma unroll
      for (int c = 0; c < 4; c++) sC[mt][nt][c] = 0.f;

  int alow = (lane & 7) + ((lane >> 3) & 1) * 8;
  int ahalf = (lane >> 4) & 1;
  int vrow = (lane & 7) + ((lane >> 3) & 1) * 8;
  int vhalf = (lane >> 4) & 1;
  int bg = w >> 2, bp = w & 3;

  for (int kc = 0; kc < 8; kc++) {
    __syncthreads();
    {
      int r = tid >> 2;
      const float* src =
          raw + (size_t)(m0 + r) * DMODEL + kc * 64 + (tid & 3) * 16;
#pragma unroll
      for (int j = 0; j < 4; j++) {
        float4 x = *(const float4*)(src + 4 * j);
        uint32_t p0 = packH2(x.x, x.y), p1 = packH2(x.z, x.w);
        int chunk = (tid & 3) * 2 + (j >> 1);
        *(uint2*)(ms + M_RAW + r * 32 + ((chunk ^ (r & 7)) << 2) +
                  ((2 * j) & 3)) = make_uint2(p0, p1);
      }
    }
    {
      int r = tid >> 2;
      int q8 = (tid & 3) * 8;
#pragma unroll
      for (int g = 0; g < 2; g++) {
        size_t srcb = ((size_t)((kc * 64 + r) * 4 + 2 * nh + g)) * 32 + q8;
        int dstb = M_BH + g * 2048 + r * 32 + q8;
        *(uint4*)(ms + dstb) = *(const uint4*)(g_w1h + srcb);
        *(uint4*)(ms + dstb + 4) = *(const uint4*)(g_w1h + srcb + 4);
        *(uint4*)(ms + dstb + 4096) = *(const uint4*)(g_w1l + srcb);
        *(uint4*)(ms + dstb + 4100) = *(const uint4*)(g_w1l + srcb + 4);
      }
    }
    __syncthreads();

#pragma unroll
    for (int kk = 0; kk < 4; kk++) {
      uint32_t af[4][4];
#pragma unroll
      for (int mt = 0; mt < 4; mt++) {
        int arow = 16 * mt + alow;
        uint32_t aa = sbm + (uint32_t)(M_RAW + arow * 32) * 4 +
                      (uint32_t)((((2 * kk + ahalf) ^ (arow & 7)) & 7) << 4);
        LDMX4(af[mt][0], af[mt][1], af[mt][2], af[mt][3], aa);
      }
      int rowt = 16 * kk + vrow;
      uint32_t ba = sbm + (uint32_t)(M_BH + bg * 2048 + rowt * 32) * 4 +
                    (uint32_t)((((2 * bp + vhalf) ^ (rowt & 7)) & 7) << 4);
      uint32_t bh0, bh1, bh2, bh3, bl0, bl1, bl2, bl3;
      LDMX4T(bh0, bh1, bh2, bh3, ba);
      LDMX4T(bl0, bl1, bl2, bl3, ba + 4096u * 4u);
#pragma unroll
      for (int mt = 0; mt < 4; mt++) {
        MMA16816(sC[mt][0], af[mt][0], af[mt][1], af[mt][2], af[mt][3], bh0, bh1);
        MMA16816(sC[mt][1], af[mt][0], af[mt][1], af[mt][2], af[mt][3], bh2, bh3);
      }
#pragma unroll
      for (int mt = 0; mt < 4; mt++) {
        MMA16816(sC[mt][0], af[mt][0], af[mt][1], af[mt][2], af[mt][3], bl0, bl1);
        MMA16816(sC[mt][1], af[mt][0], af[mt][1], af[mt][2], af[mt][3], bl2, bl3);
      }
    }
  }

  int colg = nh * 128 + bg * 64 + bp * 16 + four * 2;
  float b1v[2][2], w2v[2][2];
#pragma unroll
  for (int nt = 0; nt < 2; nt++) {
    b1v[nt][0] = b1[colg + nt * 8];
    b1v[nt][1] = b1[colg + nt * 8 + 1];
    w2v[nt][0] = w2[colg + nt * 8];
    w2v[nt][1] = w2[colg + nt * 8 + 1];
  }
  float* redf = (float*)(ms + M_RED);
#pragma unroll
  for (int mt = 0; mt < 4; mt++) {
#pragma unroll
    for (int hh = 0; hh < 2; hh++) {
      float s = 0.f;
#pragma unroll
      for (int nt = 0; nt < 2; nt++) {
        float v0 = sC[mt][nt][2 * hh] + b1v[nt][0];
        float v1 = sC[mt][nt][2 * hh + 1] + b1v[nt][1];
        s += fmaxf(v0, 0.f) * w2v[nt][0] + fmaxf(v1, 0.f) * w2v[nt][1];
      }
      s += __shfl_xor_sync(0xffffffffu, s, 1);
      s += __shfl_xor_sync(0xffffffffu, s, 2);
      if (four == 0) redf[(16 * mt + quad + 8 * hh) * 8 + w] = s;
    }
  }
  __syncthreads();
  if (tid < 64) {
    float s = 0.f;
#pragma unroll
    for (int ww = 0; ww < 8; ww++) s += redf[tid * 8 + ww];
    g_part[nh][m0 + tid] = s;
  }
}

// ============================================================================
// Kernel 3: flash attention, pure fp16 hi; h2exp2 softmax produces P
// fragments directly. 8 warps, BM=128, BN=64.
// ============================================================================
#define Bb 128
#define BNk 64

#define O_QHI 0
#define O_KHI 4096
#define O_VHI 6144
#define O_MK  8192
#define ATT_SMEM ((8192 + 64) * 4)

__global__ void __launch_bounds__(256, 2) attn_kernel(
    const float* __restrict__ at, float* __restrict__ out) {
  extern __shared__ uint32_t sm[];
  float* mk = (float*)(sm + O_MK);
  uint32_t sb = smem_u32(sm);

  int tid = threadIdx.x;
  int w = tid >> 5, lane = tid & 31;
  int quad = lane >> 2, four = lane & 3;
  int bh = blockIdx.y;
  int b = bh >> 4, h = bh & 15;
  int bx = (int)gridDim.x - 1 - (int)blockIdx.x;  // heaviest first
  int row0 = bx * Bb;

  const float sc = 0.125f * 1.44269504f;  // scale * log2(e)
  float alphaeff = at[h] * sc;

  const uint32_t* baseQ = g_q16 + ((size_t)(b * HH + h) * LL) * 32;
  const uint32_t* baseK = g_k16 + ((size_t)(b * HH + h) * LL) * 32;
  const uint32_t* baseV = g_v16 + ((size_t)(b * HH + h) * LL) * 32;

  // ---- load Q (pre-swizzled fp16): straight copy ----
  {
    int r = tid >> 1;
    int c0v = (tid & 1) * 16;
    const uint4* src = (const uint4*)(baseQ + (size_t)(row0 + r) * 32 + c0v);
    uint4* dst = (uint4*)(sm + O_QHI + r * 32 + c0v);
#pragma unroll
    for (int j = 0; j < 4; j++) dst[j] = src[j];
  }

  int arow = 16 * w + (lane & 7) + ((lane >> 3) & 1) * 8;
  int ahalf = (lane >> 4) & 1;
  int a7 = arow & 7;
  uint32_t a_base = sb + (uint32_t)(O_QHI + arow * 32) * 4;

  int krow = (lane & 7) + ((lane >> 4) & 1) * 8;
  int khalf = (lane >> 3) & 1;
  int k7 = krow & 7;
  uint32_t k_base = sb + (uint32_t)(O_KHI + krow * 32) * 4;

  int vrow = (lane & 7) + ((lane >> 3) & 1) * 8;
  int vhalf = (lane >> 4) & 1;
  int v7 = vrow & 7;
  uint32_t v_base = sb + (uint32_t)(O_VHI + vrow * 32) * 4;

  int r0g = row0 + 16 * w + quad;
  int r1g = r0g + 8;
  float mq0 = g_mom[b * LL + r0g];
  float mq1 = g_mom[b * LL + r1g];

  float oA[8][4];
#pragma unroll
  for (int nt = 0; nt < 8; nt++)
#pragma unroll
    for (int c = 0; c < 4; c++) oA[nt][c] = 0.f;
  float m0 = -CUDART_INF_F, m1 = -CUDART_INF_F, l0 = 0.f, l1 = 0.f;

  int ntiles = 2 * (bx + 1);
  for (int kt = 0; kt < ntiles; kt++) {
    int c0 = kt * BNk;
    __syncthreads();

    // ---- load K/V tiles: straight uint4 copies ----
    {
      int r = tid >> 2;
      int q8 = (tid & 3) * 8;
      size_t go = (size_t)(c0 + r) * 32 + q8;
      int so = r * 32 + q8;
      *(uint4*)(sm + O_KHI + so) = *(const uint4*)(baseK + go);
      *(uint4*)(sm + O_KHI + so + 4) = *(const uint4*)(baseK + go + 4);
      *(uint4*)(sm + O_VHI + so) = *(const uint4*)(baseV + go);
      *(uint4*)(sm + O_VHI + so + 4) = *(const uint4*)(baseV + go + 4);
    }
    if (tid < BNk) mk[tid] = g_mom[b * LL + c0 + tid];
    __syncthreads();

    // ---- S = Qhi Khi^T : 8 interleaved chains ----
    float sA[8][4];
#pragma unroll
    for (int nt = 0; nt < 8; nt++)
#pragma unroll
      for (int c = 0; c < 4; c++) sA[nt][c] = 0.f;

#pragma unroll
    for (int kk = 0; kk < 4; kk++) {
      uint32_t aq[4];
      LDMX4(aq[0], aq[1], aq[2], aq[3],
            a_base + (uint32_t)((((2 * kk + ahalf) ^ a7) & 7) << 4));
#pragma unroll
      for (int p = 0; p < 4; p++) {
        uint32_t ka = k_base + (uint32_t)(p * 2048) +
                      (uint32_t)((((2 * kk + khalf) ^ k7) & 7) << 4);
        uint32_t b0, b1v, b2v, b3;
        LDMX4(b0, b1v, b2v, b3, ka);
        MMA16816(sA[2 * p], aq[0], aq[1], aq[2], aq[3], b0, b1v);
        MMA16816(sA[2 * p + 1], aq[0], aq[1], aq[2], aq[3], b2v, b3);
      }
    }

    // ---- bias + causal mask + online softmax (base-2) ----
    float mx0 = -CUDART_INF_F, mx1 = -CUDART_INF_F;
    bool diag = (kt >= 2 * bx);
#pragma unroll
    for (int nt = 0; nt < 8; nt++) {
      int cA = nt * 8 + four * 2;
      float mkA = mk[cA], mkB = mk[cA + 1];
      float x0 = sA[nt][0] - alphaeff * fabsf(mq0 - mkA);
      float x1 = sA[nt][1] - alphaeff * fabsf(mq0 - mkB);
      float x2 = sA[nt][2] - alphaeff * fabsf(mq1 - mkA);
      float x3 = sA[nt][3] - alphaeff * fabsf(mq1 - mkB);
      if (diag) {
        int cg = c0 + cA;
        x0 = (cg <= r0g) ? x0 : -CUDART_INF_F;
        x1 = (cg + 1 <= r0g) ? x1 : -CUDART_INF_F;
        x2 = (cg <= r1g) ? x2 : -CUDART_INF_F;
        x3 = (cg + 1 <= r1g) ? x3 : -CUDART_INF_F;
      }
      sA[nt][0] = x0; sA[nt][1] = x1; sA[nt][2] = x2; sA[nt][3] = x3;
      mx0 = fmaxf(mx0, fmaxf(x0, x1));
      mx1 = fmaxf(mx1, fmaxf(x2, x3));
    }
    mx0 = fmaxf(mx0, __shfl_xor_sync(0xffffffffu, mx0, 1));
    mx0 = fmaxf(mx0, __shfl_xor_sync(0xffffffffu, mx0, 2));
    mx1 = fmaxf(mx1, __shfl_xor_sync(0xffffffffu, mx1, 1));
    mx1 = fmaxf(mx1, __shfl_xor_sync(0xffffffffu, mx1, 2));

    float mn0 = fmaxf(m0, mx0), mn1 = fmaxf(m1, mx1);
    float al0 = ex2f(m0 - mn0), al1 = ex2f(m1 - mn1);
    m0 = mn0; m1 = mn1;

    // exp in fp16 pairs: P produced directly as MMA A-fragments
    uint32_t ph[4][4];
    float rs0 = 0.f, rs1 = 0.f;
#pragma unroll
    for (int nt = 0; nt < 8; nt++) {
      __half2 ea = h2exp2(__floats2half2_rn(sA[nt][0] - mn0, sA[nt][1] - mn0));
      __half2 eb = h2exp2(__floats2half2_rn(sA[nt][2] - mn1, sA[nt][3] - mn1));
      int t = nt >> 1, j = (nt & 1) * 2;
      ph[t][j] = *(uint32_t*)&ea;
      ph[t][j + 1] = *(uint32_t*)&eb;
      float2 fa = __half22float2(ea);
      float2 fb = __half22float2(eb);
      rs0 += fa.x + fa.y;
      rs1 += fb.x + fb.y;
    }
    rs0 += __shfl_xor_sync(0xffffffffu, rs0, 1);
    rs0 += __shfl_xor_sync(0xffffffffu, rs0, 2);
    rs1 += __shfl_xor_sync(0xffffffffu, rs1, 1);
    rs1 += __shfl_xor_sync(0xffffffffu, rs1, 2);
    l0 = l0 * al0 + rs0;
    l1 = l1 * al1 + rs1;

#pragma unroll
    for (int nt = 0; nt < 8; nt++) {
      oA[nt][0] *= al0; oA[nt][1] *= al0;
      oA[nt][2] *= al1; oA[nt][3] *= al1;
    }

    // ---- O += Phi Vhi ----
#pragma unroll
    for (int t = 0; t < 4; t++) {
#pragma unroll
      for (int p = 0; p < 4; p++) {
        uint32_t va = v_base + (uint32_t)(t * 2048) +
                      (uint32_t)((((2 * p + vhalf) ^ v7) & 7) << 4);
        uint32_t b0, b1v, b2v, b3;
        LDMX4T(b0, b1v, b2v, b3, va);
        MMA16816(oA[2 * p], ph[t][0], ph[t][1], ph[t][2], ph[t][3], b0, b1v);
        MMA16816(oA[2 * p + 1], ph[t][0], ph[t][1], ph[t][2], ph[t][3], b2v, b3);
      }
    }
  }

  // ---- epilogue ----
  float inv0 = 1.f / l0, inv1 = 1.f / l1;
  float* d0p = out + ((size_t)((b * LL + r0g) * HH + h)) * DD;
  float* d1p = out + ((size_t)((b * LL + r1g) * HH + h)) * DD;
#pragma unroll
  for (int nt = 0; nt < 8; nt++) {
    int c = nt * 8 + four * 2;
    *(float2*)(d0p + c) = make_float2(oA[nt][0] * inv0, oA[nt][1] * inv0);
    *(float2*)(d1p + c) = make_float2(oA[nt][2] * inv1, oA[nt][3] * inv1);
  }
}

// ---------------------------------------------------------------------------
extern "C" void kernel_launch(void* const* d_in, const int* in_sizes, int n_in,
                              void* d_out, int out_size) {
  const float* q = (const float*)d_in[0];
  const float* k = (const float*)d_in[1];
  const float* v = (const float*)d_in[2];
  const float* raw = (const float*)d_in[3];
  const float* w1 = (const float*)d_in[4];
  const float* b1 = (const float*)d_in[5];
  const float* w2 = (const float*)d_in[6];
  const float* at = (const float*)d_in[8];
  float* out = (float*)d_out;

  wconv_kernel<<<64, 256>>>(w1);
  {
    dim3 mg(64, 2);
    mlp_tc_kernel<<<mg, 256, MLP_SMEM>>>(raw, b1, w2);
  }
  qkvconv_kernel<<<BB * LL, 256>>>(q, k, v);  // also computes g_mom

  cudaFuncSetAttribute(attn_kernel, cudaFuncAttributeMaxDynamicSharedMemorySize,
                       ATT_SMEM);
  dim3 grid(LL / Bb, BB * HH);
  attn_kernel<<<grid, 256, ATT_SMEM>>>(at, out);
}

// round 17
// speedup vs baseline: 1.0695x; 1.0695x over previous
#include <cuda_runtime.h>
#include <cuda_fp16.h>
#include <math_constants.h>
#include <cstdint>

// Problem shape (fixed)
#define BB 2
#define LL 2048
#define HH 16
#define EE 64
#define DD 64
#define DMODEL 512
#define DHID 256

__device__ float g_part[2][BB * LL];
__device__ float g_mom[BB * LL];
// w1 fp16 hi/lo, layout [k][group(0..3)][32 u32], chunk-swizzled by (k&7)
__device__ __align__(16) uint32_t g_w1h[DMODEL * 128];
__device__ __align__(16) uint32_t g_w1l[DMODEL * 128];
// fp16 hi-only, head-major, PRE-SWIZZLED: [b][h][l][32 u32]
__device__ __align__(16) uint32_t g_q16[BB * HH * LL * 32];
__device__ __align__(16) uint32_t g_k16[BB * HH * LL * 32];
__device__ __align__(16) uint32_t g_v16[BB * HH * LL * 32];

__device__ __forceinline__ void splitH2(float x0, float x1, uint32_t& hi,
                                        uint32_t& lo) {
  __half2 h = __floats2half2_rn(x0, x1);
  float2 hf = __half22float2(h);
  __half2 l = __floats2half2_rn(x0 - hf.x, x1 - hf.y);
  hi = *(uint32_t*)&h;
  lo = *(uint32_t*)&l;
}
__device__ __forceinline__ uint32_t packH2(float x0, float x1) {
  __half2 h = __floats2half2_rn(x0, x1);
  return *(uint32_t*)&h;
}
__device__ __forceinline__ float ex2f(float x) {
  float r;
  asm("ex2.approx.ftz.f32 %0, %1;" : "=f"(r) : "f"(x));
  return r;
}
__device__ __forceinline__ uint32_t smem_u32(const void* p) {
  uint32_t a;
  asm("{ .reg .u64 t; cvta.to.shared.u64 t, %1; cvt.u32.u64 %0, t; }"
      : "=r"(a) : "l"(p));
  return a;
}
__device__ __forceinline__ int swz_c(int row, int col) {
  return (col & 3) + ((((col >> 2) ^ row) & 7) << 2);
}

#define MMA16816(d, a0, a1, a2, a3, b0, b1)                                 \
  asm volatile(                                                             \
      "mma.sync.aligned.m16n8k16.row.col.f32.f16.f16.f32 "                  \
      "{%0,%1,%2,%3}, {%4,%5,%6,%7}, {%8,%9}, {%0,%1,%2,%3};"               \
      : "+f"((d)[0]), "+f"((d)[1]), "+f"((d)[2]), "+f"((d)[3])              \
      : "r"(a0), "r"(a1), "r"(a2), "r"(a3), "r"(b0), "r"(b1))

#define LDMX4(r0, r1, r2, r3, addr)                                         \
  asm volatile(                                                             \
      "ldmatrix.sync.aligned.m8n8.x4.shared.b16 {%0,%1,%2,%3}, [%4];"       \
      : "=r"(r0), "=r"(r1), "=r"(r2), "=r"(r3) : "r"(addr))

#define LDMX4T(r0, r1, r2, r3, addr)                                        \
  asm volatile(                                                             \
      "ldmatrix.sync.aligned.m8n8.x4.trans.shared.b16 {%0,%1,%2,%3}, [%4];" \
      : "=r"(r0), "=r"(r1), "=r"(r2), "=r"(r3) : "r"(addr))

#define CPA16(saddr, gptr)                                                  \
  asm volatile("cp.async.ca.shared.global [%0], [%1], 16;"                  \
               :: "r"(saddr), "l"(gptr) : "memory")
#define CPA_COMMIT() asm volatile("cp.async.commit_group;" ::: "memory")
#define CPA_WAIT(n) asm volatile("cp.async.wait_group %0;" :: "n"(n) : "memory")

// ============================================================================
// Kernel 0a: convert w1 to fp16 hi/lo scratch (for MLP)
// ============================================================================
__global__ __launch_bounds__(256) void wconv_kernel(const float* __restrict__ w1) {
  int idx = blockIdx.x * 256 + threadIdx.x;
  int k = idx >> 5;
  int r5 = idx & 31;
  int g = r5 >> 3, ch = r5 & 7;
  const float4* src = (const float4*)(w1 + (size_t)k * DHID + g * 64 + ch * 8);
  float4 a = src[0], b = src[1];
  uint32_t h0, l0, h1, l1, h2, l2, h3, l3;
  splitH2(a.x, a.y, h0, l0);
  splitH2(a.z, a.w, h1, l1);
  splitH2(b.x, b.y, h2, l2);
  splitH2(b.z, b.w, h3, l3);
  size_t dst = ((size_t)(k * 4 + g)) * 32 + ((ch ^ (k & 7)) << 2);
  *(uint4*)(g_w1h + dst) = make_uint4(h0, h1, h2, h3);
  *(uint4*)(g_w1l + dst) = make_uint4(l0, l1, l2, l3);
}

// ============================================================================
// Kernel 0b: convert Q*sc/K/V to fp16 hi-only (pre-swizzled) + momentum.
// ============================================================================
__global__ __launch_bounds__(256) void qkvconv_kernel(
    const float* __restrict__ qg, const float* __restrict__ kg,
    const float* __restrict__ vg) {
  int bl = blockIdx.x;
  int b = bl >> 11, l = bl & 2047;
  int tid = threadIdx.x;
  int h = tid >> 4;
  int e4 = tid & 15;

  const float sc = 0.125f * 1.44269504f;
  size_t gsrc = ((size_t)(b * LL + l) * HH + h) * EE + e4 * 4;
  size_t gdst = ((size_t)(b * HH + h) * LL + l) * 32;
  int scol = swz_c(l & 7, 2 * e4);

  float4 xq = *(const float4*)(qg + gsrc);
  *(uint2*)(g_q16 + gdst + scol) =
      make_uint2(packH2(xq.x * sc, xq.y * sc), packH2(xq.z * sc, xq.w * sc));
  float4 xk = *(const float4*)(kg + gsrc);
  *(uint2*)(g_k16 + gdst + scol) =
      make_uint2(packH2(xk.x, xk.y), packH2(xk.z, xk.w));
  float4 xv = *(const float4*)(vg + gsrc);
  *(uint2*)(g_v16 + gdst + scol) =
      make_uint2(packH2(xv.x, xv.y), packH2(xv.z, xv.w));

  if (tid == 0) {
    float m = 0.f;
    if (l > 0)
      m = (g_part[0][bl] + g_part[1][bl]) -
          (g_part[0][bl - 1] + g_part[1][bl - 1]);
    g_mom[bl] = m;
  }
}

// ============================================================================
// Kernel 1: tensor-core MLP, N-split (unchanged)
// ============================================================================
#define M_RAW 0
#define M_BH 2048
#define M_BL 6144
#define M_RED 10240
#define MLP_SMEM ((10240 + 512) * 4)

__global__ __launch_bounds__(256) void mlp_tc_kernel(
    const float* __restrict__ raw, const float* __restrict__ b1,
    const float* __restrict__ w2) {
  extern __shared__ uint32_t ms[];
  uint32_t sbm = smem_u32(ms);
  int tid = threadIdx.x;
  int w = tid >> 5, lane = tid & 31;
  int quad = lane >> 2, four = lane & 3;
  int m0 = blockIdx.x * 64;
  int nh = blockIdx.y;

  float sC[4][2][4];
#pragma unroll
  for (int mt = 0; mt < 4; mt++)
#pragma unroll
    for (int nt = 0; nt < 2; nt++)
#pragma unroll
      for (int c = 0; c < 4; c++) sC[mt][nt][c] = 0.f;

  int alow = (lane & 7) + ((lane >> 3) & 1) * 8;
  int ahalf = (lane >> 4) & 1;
  int vrow = (lane & 7) + ((lane >> 3) & 1) * 8;
  int vhalf = (lane >> 4) & 1;
  int bg = w >> 2, bp = w & 3;

  for (int kc = 0; kc < 8; kc++) {
    __syncthreads();
    {
      int r = tid >> 2;
      const float* src =
          raw + (size_t)(m0 + r) * DMODEL + kc * 64 + (tid & 3) * 16;
#pragma unroll
      for (int j = 0; j < 4; j++) {
        float4 x = *(const float4*)(src + 4 * j);
        uint32_t p0 = packH2(x.x, x.y), p1 = packH2(x.z, x.w);
        int chunk = (tid & 3) * 2 + (j >> 1);
        *(uint2*)(ms + M_RAW + r * 32 + ((chunk ^ (r & 7)) << 2) +
                  ((2 * j) & 3)) = make_uint2(p0, p1);
      }
    }
    {
      int r = tid >> 2;
      int q8 = (tid & 3) * 8;
#pragma unroll
      for (int g = 0; g < 2; g++) {
        size_t srcb = ((size_t)((kc * 64 + r) * 4 + 2 * nh + g)) * 32 + q8;
        int dstb = M_BH + g * 2048 + r * 32 + q8;
        *(uint4*)(ms + dstb) = *(const uint4*)(g_w1h + srcb);
        *(uint4*)(ms + dstb + 4) = *(const uint4*)(g_w1h + srcb + 4);
        *(uint4*)(ms + dstb + 4096) = *(const uint4*)(g_w1l + srcb);
        *(uint4*)(ms + dstb + 4100) = *(const uint4*)(g_w1l + srcb + 4);
      }
    }
    __syncthreads();

#pragma unroll
    for (int kk = 0; kk < 4; kk++) {
      uint32_t af[4][4];
#pragma unroll
      for (int mt = 0; mt < 4; mt++) {
        int arow = 16 * mt + alow;
        uint32_t aa = sbm + (uint32_t)(M_RAW + arow * 32) * 4 +
                      (uint32_t)((((2 * kk + ahalf) ^ (arow & 7)) & 7) << 4);
        LDMX4(af[mt][0], af[mt][1], af[mt][2], af[mt][3], aa);
      }
      int rowt = 16 * kk + vrow;
      uint32_t ba = sbm + (uint32_t)(M_BH + bg * 2048 + rowt * 32) * 4 +
                    (uint32_t)((((2 * bp + vhalf) ^ (rowt & 7)) & 7) << 4);
      uint32_t bh0, bh1, bh2, bh3, bl0, bl1, bl2, bl3;
      LDMX4T(bh0, bh1, bh2, bh3, ba);
      LDMX4T(bl0, bl1, bl2, bl3, ba + 4096u * 4u);
#pragma unroll
      for (int mt = 0; mt < 4; mt++) {
        MMA16816(sC[mt][0], af[mt][0], af[mt][1], af[mt][2], af[mt][3], bh0, bh1);
        MMA16816(sC[mt][1], af[mt][0], af[mt][1], af[mt][2], af[mt][3], bh2, bh3);
      }
#pragma unroll
      for (int mt = 0; mt < 4; mt++) {
        MMA16816(sC[mt][0], af[mt][0], af[mt][1], af[mt][2], af[mt][3], bl0, bl1);
        MMA16816(sC[mt][1], af[mt][0], af[mt][1], af[mt][2], af[mt][3], bl2, bl3);
      }
    }
  }

  int colg = nh * 128 + bg * 64 + bp * 16 + four * 2;
  float b1v[2][2], w2v[2][2];
#pragma unroll
  for (int nt = 0; nt < 2; nt++) {
    b1v[nt][0] = b1[colg + nt * 8];
    b1v[nt][1] = b1[colg + nt * 8 + 1];
    w2v[nt][0] = w2[colg + nt * 8];
    w2v[nt][1] = w2[colg + nt * 8 + 1];
  }
  float* redf = (float*)(ms + M_RED);
#pragma unroll
  for (int mt = 0; mt < 4; mt++) {
#pragma unroll
    for (int hh = 0; hh < 2; hh++) {
      float s = 0.f;
#pragma unroll
      for (int nt = 0; nt < 2; nt++) {
        float v0 = sC[mt][nt][2 * hh] + b1v[nt][0];
        float v1 = sC[mt][nt][2 * hh + 1] + b1v[nt][1];
        s += fmaxf(v0, 0.f) * w2v[nt][0] + fmaxf(v1, 0.f) * w2v[nt][1];
      }
      s += __shfl_xor_sync(0xffffffffu, s, 1);
      s += __shfl_xor_sync(0xffffffffu, s, 2);
      if (four == 0) redf[(16 * mt + quad + 8 * hh) * 8 + w] = s;
    }
  }
  __syncthreads();
  if (tid < 64) {
    float s = 0.f;
#pragma unroll
    for (int ww = 0; ww < 8; ww++) s += redf[tid * 8 + ww];
    g_part[nh][m0 + tid] = s;
  }
}

// ============================================================================
// Kernel 3: flash attention, fp16-hi, cp.async double-buffered K/V tiles,
// h2exp2 softmax. 8 warps, BM=128, BN=64.
// ============================================================================
#define Bb 128
#define BNk 64

// smem u32 offsets: Q[4096] + 2 stages of (K 2048 + V 2048 + mk 64 + pad)
#define O_QHI 0
#define STG 4224
#define O_ST0 4096
#define O_ST1 (O_ST0 + STG)
#define SKH 0
#define SVH 2048
#define SMK 4096
#define ATT_SMEM ((O_ST1 + STG) * 4)

__global__ void __launch_bounds__(256, 2) attn_kernel(
    const float* __restrict__ at, float* __restrict__ out) {
  extern __shared__ uint32_t sm[];
  uint32_t sb = smem_u32(sm);

  int tid = threadIdx.x;
  int w = tid >> 5, lane = tid & 31;
  int quad = lane >> 2, four = lane & 3;
  int bh = blockIdx.y;
  int b = bh >> 4, h = bh & 15;
  int bx = (int)gridDim.x - 1 - (int)blockIdx.x;  // heaviest first
  int row0 = bx * Bb;

  float alphaeff = at[h] * (0.125f * 1.44269504f);

  const uint32_t* baseQ = g_q16 + ((size_t)(b * HH + h) * LL) * 32;
  const uint32_t* baseK = g_k16 + ((size_t)(b * HH + h) * LL) * 32;
  const uint32_t* baseV = g_v16 + ((size_t)(b * HH + h) * LL) * 32;
  const float* momB = g_mom + b * LL;

  // ---- Q copy via cp.async (group with tile 0) ----
  {
    int r = tid >> 1;
    int c0v = (tid & 1) * 16;
    uint32_t dst = sb + (uint32_t)(O_QHI + r * 32 + c0v) * 4;
    const uint32_t* src = baseQ + (size_t)(row0 + r) * 32 + c0v;
#pragma unroll
    for (int j = 0; j < 4; j++) CPA16(dst + 16 * j, src + 4 * j);
  }
// prefetch tile (c0v) into stage stg
#define PREFETCH(c0v, stg)                                                    \
  do {                                                                        \
    int r = tid >> 2;                                                         \
    int q8 = (tid & 3) * 8;                                                   \
    size_t go = (size_t)((c0v) + r) * 32 + q8;                                \
    uint32_t so = sb + (uint32_t)((stg) + r * 32 + q8) * 4;                   \
    CPA16(so, baseK + go);                                                    \
    CPA16(so + 16, baseK + go + 4);                                           \
    CPA16(so + (uint32_t)(SVH * 4), baseV + go);                              \
    CPA16(so + (uint32_t)(SVH * 4) + 16, baseV + go + 4);                     \
    if (tid < 16)                                                             \
      CPA16(sb + (uint32_t)((stg) + SMK) * 4 + tid * 16,                      \
            momB + (c0v) + tid * 4);                                          \
  } while (0)

  PREFETCH(0, O_ST0);
  CPA_COMMIT();

  int arow = 16 * w + (lane & 7) + ((lane >> 3) & 1) * 8;
  int ahalf = (lane >> 4) & 1;
  int a7 = arow & 7;
  uint32_t a_base = sb + (uint32_t)(O_QHI + arow * 32) * 4;

  int krow = (lane & 7) + ((lane >> 4) & 1) * 8;
  int khalf = (lane >> 3) & 1;
  int k7 = krow & 7;
  int vrow = (lane & 7) + ((lane >> 3) & 1) * 8;
  int vhalf = (lane >> 4) & 1;
  int v7 = vrow & 7;

  int r0g = row0 + 16 * w + quad;
  int r1g = r0g + 8;
  float mq0 = momB[r0g];
  float mq1 = momB[r1g];

  float oA[8][4];
#pragma unroll
  for (int nt = 0; nt < 8; nt++)
#pragma unroll
    for (int c = 0; c < 4; c++) oA[nt][c] = 0.f;
  float m0 = -CUDART_INF_F, m1 = -CUDART_INF_F, l0 = 0.f, l1 = 0.f;

  int ntiles = 2 * (bx + 1);
  for (int kt = 0; kt < ntiles; kt++) {
    int c0 = kt * BNk;
    int stg = (kt & 1) ? O_ST1 : O_ST0;

    if (kt + 1 < ntiles) {
      // all threads finished computing from the other stage (previous iter's
      // trailing compute has no smem reads after its last ldmatrix; the
      // barrier below orders refill vs those reads)
      __syncthreads();
      PREFETCH(c0 + BNk, (kt & 1) ? O_ST0 : O_ST1);
      CPA_COMMIT();
      CPA_WAIT(1);
    } else {
      __syncthreads();
      CPA_WAIT(0);
    }
    __syncthreads();  // stage kt visible

    uint32_t k_base = sb + (uint32_t)(stg + SKH + krow * 32) * 4;
    uint32_t v_base = sb + (uint32_t)(stg + SVH + vrow * 32) * 4;
    float* mk = (float*)(sm + stg + SMK);

    // ---- S = Qhi Khi^T ----
    float sA[8][4];
#pragma unroll
    for (int nt = 0; nt < 8; nt++)
#pragma unroll
      for (int c = 0; c < 4; c++) sA[nt][c] = 0.f;

#pragma unroll
    for (int kk = 0; kk < 4; kk++) {
      uint32_t aq[4];
      LDMX4(aq[0], aq[1], aq[2], aq[3],
            a_base + (uint32_t)((((2 * kk + ahalf) ^ a7) & 7) << 4));
#pragma unroll
      for (int p = 0; p < 4; p++) {
        uint32_t ka = k_base + (uint32_t)(p * 2048) +
                      (uint32_t)((((2 * kk + khalf) ^ k7) & 7) << 4);
        uint32_t b0, b1v, b2v, b3;
        LDMX4(b0, b1v, b2v, b3, ka);
        MMA16816(sA[2 * p], aq[0], aq[1], aq[2], aq[3], b0, b1v);
        MMA16816(sA[2 * p + 1], aq[0], aq[1], aq[2], aq[3], b2v, b3);
      }
    }

    // ---- bias + causal mask + online softmax (base-2) ----
    float mx0 = -CUDART_INF_F, mx1 = -CUDART_INF_F;
    bool diag = (kt >= 2 * bx);
#pragma unroll
    for (int nt = 0; nt < 8; nt++) {
      int cA = nt * 8 + four * 2;
      float mkA = mk[cA], mkB = mk[cA + 1];
      float x0 = sA[nt][0] - alphaeff * fabsf(mq0 - mkA);
      float x1 = sA[nt][1] - alphaeff * fabsf(mq0 - mkB);
      float x2 = sA[nt][2] - alphaeff * fabsf(mq1 - mkA);
      float x3 = sA[nt][3] - alphaeff * fabsf(mq1 - mkB);
      if (diag) {
        int cg = c0 + cA;
        x0 = (cg <= r0g) ? x0 : -CUDART_INF_F;
        x1 = (cg + 1 <= r0g) ? x1 : -CUDART_INF_F;
        x2 = (cg <= r1g) ? x2 : -CUDART_INF_F;
        x3 = (cg + 1 <= r1g) ? x3 : -CUDART_INF_F;
      }
      sA[nt][0] = x0; sA[nt][1] = x1; sA[nt][2] = x2; sA[nt][3] = x3;
      mx0 = fmaxf(mx0, fmaxf(x0, x1));
      mx1 = fmaxf(mx1, fmaxf(x2, x3));
    }
    mx0 = fmaxf(mx0, __shfl_xor_sync(0xffffffffu, mx0, 1));
    mx0 = fmaxf(mx0, __shfl_xor_sync(0xffffffffu, mx0, 2));
    mx1 = fmaxf(mx1, __shfl_xor_sync(0xffffffffu, mx1, 1));
    mx1 = fmaxf(mx1, __shfl_xor_sync(0xffffffffu, mx1, 2));

    float mn0 = fmaxf(m0, mx0), mn1 = fmaxf(m1, mx1);
    float al0 = ex2f(m0 - mn0), al1 = ex2f(m1 - mn1);
    m0 = mn0; m1 = mn1;

    uint32_t ph[4][4];
    float rs0 = 0.f, rs1 = 0.f;
#pragma unroll
    for (int nt = 0; nt < 8; nt++) {
      __half2 ea = h2exp2(__floats2half2_rn(sA[nt][0] - mn0, sA[nt][1] - mn0));
      __half2 eb = h2exp2(__floats2half2_rn(sA[nt][2] - mn1, sA[nt][3] - mn1));
      int t = nt >> 1, j = (nt & 1) * 2;
      ph[t][j] = *(uint32_t*)&ea;
      ph[t][j + 1] = *(uint32_t*)&eb;
      float2 fa = __half22float2(ea);
      float2 fb = __half22float2(eb);
      rs0 += fa.x + fa.y;
      rs1 += fb.x + fb.y;
    }
    rs0 += __shfl_xor_sync(0xffffffffu, rs0, 1);
    rs0 += __shfl_xor_sync(0xffffffffu, rs0, 2);
    rs1 += __shfl_xor_sync(0xffffffffu, rs1, 1);
    rs1 += __shfl_xor_sync(0xffffffffu, rs1, 2);
    l0 = l0 * al0 + rs0;
    l1 = l1 * al1 + rs1;

#pragma unroll
    for (int nt = 0; nt < 8; nt++) {
      oA[nt][0] *= al0; oA[nt][1] *= al0;
      oA[nt][2] *= al1; oA[nt][3] *= al1;
    }

    // ---- O += Phi Vhi ----
#pragma unroll
    for (int t = 0; t < 4; t++) {
#pragma unroll
      for (int p = 0; p < 4; p++) {
        uint32_t va = v_base + (uint32_t)(t * 2048) +
                      (uint32_t)((((2 * p + vhalf) ^ v7) & 7) << 4);
        uint32_t b0, b1v, b2v, b3;
        LDMX4T(b0, b1v, b2v, b3, va);
        MMA16816(oA[2 * p], ph[t][0], ph[t][1], ph[t][2], ph[t][3], b0, b1v);
        MMA16816(oA[2 * p + 1], ph[t][0], ph[t][1], ph[t][2], ph[t][3], b2v, b3);
      }
    }
  }

  // ---- epilogue ----
  float inv0 = 1.f / l0, inv1 = 1.f / l1;
  float* d0p = out + ((size_t)((b * LL + r0g) * HH + h)) * DD;
  float* d1p = out + ((size_t)((b * LL + r1g) * HH + h)) * DD;
#pragma unroll
  for (int nt = 0; nt < 8; nt++) {
    int c = nt * 8 + four * 2;
    *(float2*)(d0p + c) = make_float2(oA[nt][0] * inv0, oA[nt][1] * inv0);
    *(float2*)(d1p + c) = make_float2(oA[nt][2] * inv1, oA[nt][3] * inv1);
  }
}

// ---------------------------------------------------------------------------
extern "C" void kernel_launch(void* const* d_in, const int* in_sizes, int n_in,
                              void* d_out, int out_size) {
  const float* q = (const float*)d_in[0];
  const float* k = (const float*)d_in[1];
  const float* v = (const float*)d_in[2];
  const float* raw = (const float*)d_in[3];
  const float* w1 = (const float*)d_in[4];
  const float* b1 = (const float*)d_in[5];
  const float* w2 = (const float*)d_in[6];
  const float* at = (const float*)d_in[8];
  float* out = (float*)d_out;

  wconv_kernel<<<64, 256>>>(w1);
  {
    dim3 mg(64, 2);
    mlp_tc_kernel<<<mg, 256, MLP_SMEM>>>(raw, b1, w2);
  }
  qkvconv_kernel<<<BB * LL, 256>>>(q, k, v);  // also computes g_mom

  cudaFuncSetAttribute(attn_kernel, cudaFuncAttributeMaxDynamicSharedMemorySize,
                       ATT_SMEM);
  dim3 grid(LL / Bb, BB * HH);
  attn_kernel<<<grid, 256, ATT_SMEM>>>(at, out);
}